// round 12
// baseline (speedup 1.0000x reference)
#include <cuda_runtime.h>
#include <cstdint>

// Shapes (fixed)
constexpr int B_   = 2;
constexpr int C_   = 64;
constexpr int CQK_ = 8;
constexpr int N_   = 4096;

constexpr int KS2 = 8;       // key splits
constexpr int MT  = 128;     // queries per CTA (8 warps x m16)
constexpr int NK  = 64;      // keys staged per tile (smaller => 3 CTAs/SM)
constexpr int VSTRIDE = 72;  // padded floats per key row in smem (conflict-free)

// ---------------- scratch ----------------
__device__ float g_q[B_ * N_ * CQK_];          // [B][N][8] (pre-scaled by log2e)
__device__ float g_k[B_ * N_ * CQK_];          // [B][N][8]
__device__ float g_v[B_ * N_ * C_];            // [B][N][64] key-major, tf32-rounded
__device__ float g_pacc[B_ * KS2 * N_ * C_];   // [B][S][q][64]
__device__ float g_pden[B_ * KS2 * N_];        // [B][S][q]

// ---------------- helpers ----------------
__device__ __forceinline__ unsigned long long fma2(unsigned long long a, unsigned long long b, unsigned long long c) {
    unsigned long long d;
    asm("fma.rn.f32x2 %0, %1, %2, %3;" : "=l"(d) : "l"(a), "l"(b), "l"(c));
    return d;
}
__device__ __forceinline__ unsigned long long mul2(unsigned long long a, unsigned long long b) {
    unsigned long long d;
    asm("mul.rn.f32x2 %0, %1, %2;" : "=l"(d) : "l"(a), "l"(b));
    return d;
}
__device__ __forceinline__ unsigned long long pack2(float lo, float hi) {
    unsigned long long r;
    asm("mov.b64 %0, {%1, %2};" : "=l"(r) : "f"(lo), "f"(hi));
    return r;
}
__device__ __forceinline__ float hadd2(unsigned long long a) {
    float lo, hi;
    asm("mov.b64 {%0, %1}, %2;" : "=f"(lo), "=f"(hi) : "l"(a));
    return lo + hi;
}
__device__ __forceinline__ float ex2f(float x) {
    float r;
    asm("ex2.approx.f32 %0, %1;" : "=f"(r) : "f"(x));
    return r;
}
__device__ __forceinline__ uint32_t f2tf32(float f) {
    uint32_t r;
    asm("cvt.rna.tf32.f32 %0, %1;" : "=r"(r) : "f"(f));
    return r;
}
// D[16x8] += A[16x8, tf32 row] * B[8x8, tf32 col]; accumulate in place
__device__ __forceinline__ void mma_tf32(float* d, const uint32_t* a, uint32_t b0, uint32_t b1) {
    asm volatile(
        "mma.sync.aligned.m16n8k8.row.col.f32.tf32.tf32.f32 "
        "{%0,%1,%2,%3}, {%4,%5,%6,%7}, {%8,%9}, {%0,%1,%2,%3};"
        : "+f"(d[0]), "+f"(d[1]), "+f"(d[2]), "+f"(d[3])
        : "r"(a[0]), "r"(a[1]), "r"(a[2]), "r"(a[3]), "r"(b0), "r"(b1));
}

// ============================================================================
// Kernel 1: QKV projection. Grid (256, 2) x 128 threads.
//  y=0: w0=q[0:8], w1=k[0:8], w2=v[0:8],  w3=v[8:16]
//  y=1: w0=v[16:28], w1=v[28:40], w2=v[40:52], w3=v[52:64]
// Two-pass over input channels (xr[32] twice) to halve register pressure.
// q pre-scaled by log2(e); V stored key-major [B][N][64], tf32-rounded.
// ============================================================================
__global__ __launch_bounds__(128) void qkv_kernel(
    const float* __restrict__ x,
    const float* __restrict__ Wq, const float* __restrict__ bq,
    const float* __restrict__ Wk, const float* __restrict__ bk,
    const float* __restrict__ Wv, const float* __restrict__ bv)
{
    __shared__ float swq[CQK_ * C_], swk[CQK_ * C_], swv[C_ * C_];
    __shared__ float sbq[CQK_], sbk[CQK_], sbv[C_];
    const int tid = threadIdx.x, wid = tid >> 5, lid = tid & 31;
    const int y = blockIdx.y;

    if (y == 0) {
        for (int i = tid; i < CQK_ * C_; i += 128) { swq[i] = Wq[i]; swk[i] = Wk[i]; }
        for (int i = tid; i < 16 * C_; i += 128) { swv[i] = Wv[i]; }
        if (tid < CQK_) { sbq[tid] = bq[tid]; sbk[tid] = bk[tid]; }
        if (tid < 16)   { sbv[tid] = bv[tid]; }
    } else {
        for (int i = tid; i < 48 * C_; i += 128) { swv[16 * C_ + i] = Wv[16 * C_ + i]; }
        if (tid < 48) { sbv[16 + tid] = bv[16 + tid]; }
    }
    __syncthreads();

    const int pos = blockIdx.x * 32 + lid;     // b*N + n
    const int b = pos >> 12;
    const int n = pos & (N_ - 1);
    const float* xb = x + (size_t)b * C_ * N_ + n;

    if (y == 0 && wid < 2) {
        const float* W  = wid ? swk : swq;
        const float* bb = wid ? sbk : sbq;
        const float scale = wid ? 1.0f : 1.44269504088896f;   // log2(e) into q
        float o[CQK_];
#pragma unroll
        for (int j = 0; j < CQK_; j++) o[j] = bb[j];
#pragma unroll
        for (int half = 0; half < 2; half++) {
            float xr[32];
#pragma unroll
            for (int c = 0; c < 32; c++) xr[c] = xb[(size_t)(half * 32 + c) * N_];
#pragma unroll
            for (int j = 0; j < CQK_; j++) {
                float a = 0.f;
#pragma unroll
                for (int c = 0; c < 32; c++) a += W[j * C_ + half * 32 + c] * xr[c];
                o[j] += a;
            }
        }
        float* dst = (wid ? g_k : g_q) + (size_t)pos * CQK_;
        ((float4*)dst)[0] = make_float4(o[0] * scale, o[1] * scale, o[2] * scale, o[3] * scale);
        ((float4*)dst)[1] = make_float4(o[4] * scale, o[5] * scale, o[6] * scale, o[7] * scale);
        return;
    }

    int c0, cnt;
    if (y == 0) { c0 = (wid - 2) * 8; cnt = 8; }       // v[0:8], v[8:16]
    else        { c0 = 16 + wid * 12; cnt = 12; }      // v[16:64] in 12s

    float acc[12];
#pragma unroll
    for (int j = 0; j < 12; j++) acc[j] = (j < cnt) ? sbv[c0 + j] : 0.f;

#pragma unroll
    for (int half = 0; half < 2; half++) {
        float xr[32];
#pragma unroll
        for (int c = 0; c < 32; c++) xr[c] = xb[(size_t)(half * 32 + c) * N_];
        for (int j = 0; j < cnt; j++) {
            float a = 0.f;
#pragma unroll
            for (int c = 0; c < 32; c++) a += swv[(c0 + j) * C_ + half * 32 + c] * xr[c];
            acc[j] += a;
        }
    }

    float* vo = g_v + (size_t)pos * C_;
    for (int jj = 0; jj < cnt; jj += 4) {
        *(float4*)(vo + c0 + jj) = make_float4(
            __uint_as_float(f2tf32(acc[jj])),     __uint_as_float(f2tf32(acc[jj + 1])),
            __uint_as_float(f2tf32(acc[jj + 2])), __uint_as_float(f2tf32(acc[jj + 3])));
    }
}

// ============================================================================
// Kernel 2: flash attention, PV on mma.sync tf32 (m16n8k8).
// Grid (N/MT=32, KS2=8, B=2), 256 threads = 8 warps; warp w owns queries
// [16w, 16w+16). NK=64 key tile (20.5 KB smem) so 3 CTAs fit per SM.
// ============================================================================
__global__ __launch_bounds__(256, 3) void attn_mma_kernel()
{
    __shared__ float4 skt[NK * 2];                // K tile [64 keys][8]  (2 KB)
    __shared__ float  svt[NK * VSTRIDE];          // V tile [64 keys][72] (18 KB)

    const int tid = threadIdx.x, wid = tid >> 5, lane = tid & 31;
    const int b = blockIdx.z, sp = blockIdx.y, qt = blockIdx.x;
    const int grp = lane >> 2;        // 0..7
    const int cq  = lane & 3;         // 0..3

    const int q0g = qt * MT + wid * 16 + grp;     // r0
    const int q1g = q0g + 8;                      // r1

    const float4* qp0 = (const float4*)(g_q + ((size_t)b * N_ + q0g) * CQK_);
    const float4* qp1 = (const float4*)(g_q + ((size_t)b * N_ + q1g) * CQK_);
    const float4 qa0 = qp0[0], qa1 = qp0[1], qb0 = qp1[0], qb1 = qp1[1];
    const unsigned long long qq0[4] = { pack2(qa0.x, qa0.y), pack2(qa0.z, qa0.w),
                                        pack2(qa1.x, qa1.y), pack2(qa1.z, qa1.w) };
    const unsigned long long qq1[4] = { pack2(qb0.x, qb0.y), pack2(qb0.z, qb0.w),
                                        pack2(qb1.x, qb1.y), pack2(qb1.z, qb1.w) };

    float d[8][4];
#pragma unroll
    for (int j = 0; j < 8; j++) { d[j][0] = d[j][1] = d[j][2] = d[j][3] = 0.0f; }
    float den0 = 0.0f, den1 = 0.0f;

    const int kbase0 = sp * (N_ / KS2);
    for (int t = 0; t < (N_ / KS2) / NK; t++) {
        const int kstart = kbase0 + t * NK;
        __syncthreads();
        // stage K: 128 float4 (threads 0-127)
        const float4* kg = (const float4*)(g_k + ((size_t)b * N_ + kstart) * CQK_);
        if (tid < NK * 2) skt[tid] = kg[tid];
        // stage V: 1024 float4 -> [key][72]
        const float4* vg = (const float4*)(g_v + ((size_t)b * N_ + kstart) * C_);
#pragma unroll
        for (int i = tid; i < NK * 16; i += 256) {
            const int key = i >> 4, c4 = i & 15;
            *(float4*)(svt + key * VSTRIDE + c4 * 4) = vg[i];
        }
        __syncthreads();

#pragma unroll 4
        for (int s = 0; s < NK / 8; s++) {
            const int k0 = s * 8;
            const float4 kA0 = skt[(k0 + cq) * 2],     kA1 = skt[(k0 + cq) * 2 + 1];
            const float4 kB0 = skt[(k0 + cq + 4) * 2], kB1 = skt[(k0 + cq + 4) * 2 + 1];
            const unsigned long long kAp[4] = { pack2(kA0.x, kA0.y), pack2(kA0.z, kA0.w),
                                                pack2(kA1.x, kA1.y), pack2(kA1.z, kA1.w) };
            const unsigned long long kBp[4] = { pack2(kB0.x, kB0.y), pack2(kB0.z, kB0.w),
                                                pack2(kB1.x, kB1.y), pack2(kB1.z, kB1.w) };

            unsigned long long e;
            e = mul2(qq0[3], kAp[3]); e = fma2(qq0[2], kAp[2], e);
            e = fma2(qq0[1], kAp[1], e); e = fma2(qq0[0], kAp[0], e);
            const float p00 = ex2f(hadd2(e));
            e = mul2(qq1[3], kAp[3]); e = fma2(qq1[2], kAp[2], e);
            e = fma2(qq1[1], kAp[1], e); e = fma2(qq1[0], kAp[0], e);
            const float p10 = ex2f(hadd2(e));
            e = mul2(qq0[3], kBp[3]); e = fma2(qq0[2], kBp[2], e);
            e = fma2(qq0[1], kBp[1], e); e = fma2(qq0[0], kBp[0], e);
            const float p01 = ex2f(hadd2(e));
            e = mul2(qq1[3], kBp[3]); e = fma2(qq1[2], kBp[2], e);
            e = fma2(qq1[1], kBp[1], e); e = fma2(qq1[0], kBp[0], e);
            const float p11 = ex2f(hadd2(e));

            den0 += p00 + p01;
            den1 += p10 + p11;

            const uint32_t a[4] = { f2tf32(p00), f2tf32(p10), f2tf32(p01), f2tf32(p11) };

            const float* vr0 = svt + (k0 + cq) * VSTRIDE + grp;
            const float* vr1 = vr0 + 4 * VSTRIDE;
#pragma unroll
            for (int j = 0; j < 8; j++) {
                mma_tf32(d[j], a, __float_as_uint(vr0[8 * j]), __float_as_uint(vr1[8 * j]));
            }
        }
    }

    den0 += __shfl_xor_sync(0xFFFFFFFFu, den0, 1);
    den0 += __shfl_xor_sync(0xFFFFFFFFu, den0, 2);
    den1 += __shfl_xor_sync(0xFFFFFFFFu, den1, 1);
    den1 += __shfl_xor_sync(0xFFFFFFFFu, den1, 2);

    float* p0 = g_pacc + (((size_t)(b * KS2 + sp) * N_) + q0g) * C_;
    float* p1 = g_pacc + (((size_t)(b * KS2 + sp) * N_) + q1g) * C_;
#pragma unroll
    for (int j = 0; j < 8; j++) {
        *(float2*)(p0 + 8 * j + 2 * cq) = make_float2(d[j][0], d[j][1]);
        *(float2*)(p1 + 8 * j + 2 * cq) = make_float2(d[j][2], d[j][3]);
    }
    if (cq == 0) {
        g_pden[(size_t)(b * KS2 + sp) * N_ + q0g] = den0;
        g_pden[(size_t)(b * KS2 + sp) * N_ + q1g] = den1;
    }
}

// ============================================================================
// Kernel 3: combine KS2 split partials + residual.
// Grid (64, 4) x 128: thread = (b, n), blockIdx.y = channel quarter.
// ============================================================================
__global__ __launch_bounds__(128) void combine_kernel(
    const float* __restrict__ x,
    const float* __restrict__ gamma,
    float* __restrict__ out)
{
    const int t = blockIdx.x * 128 + threadIdx.x;   // 0..B*N-1
    const int b = t >> 12;
    const int n = t & (N_ - 1);
    const int c4base = blockIdx.y * 4;              // 4 c4-chunks per block row

    float den = 0.0f;
#pragma unroll
    for (int s = 0; s < KS2; s++) den += g_pden[(size_t)(b * KS2 + s) * N_ + n];
    const float scale = gamma[0] / den;

#pragma unroll
    for (int c4 = c4base; c4 < c4base + 4; c4++) {
        float sx = 0.f, sy = 0.f, sz = 0.f, sw = 0.f;
#pragma unroll
        for (int s = 0; s < KS2; s++) {
            const float4 u = ((const float4*)(g_pacc + (((size_t)(b * KS2 + s) * N_) + n) * C_))[c4];
            sx += u.x; sy += u.y; sz += u.z; sw += u.w;
        }
        size_t o = ((size_t)b * C_ + c4 * 4) * N_ + n;
        out[o] = fmaf(scale, sx, x[o]); o += N_;
        out[o] = fmaf(scale, sy, x[o]); o += N_;
        out[o] = fmaf(scale, sz, x[o]); o += N_;
        out[o] = fmaf(scale, sw, x[o]);
    }
}

// ============================================================================
extern "C" void kernel_launch(void* const* d_in, const int* in_sizes, int n_in,
                              void* d_out, int out_size)
{
    const float* x     = (const float*)d_in[0];
    const float* Wq    = (const float*)d_in[1];
    const float* bq    = (const float*)d_in[2];
    const float* Wk    = (const float*)d_in[3];
    const float* bk    = (const float*)d_in[4];
    const float* Wv    = (const float*)d_in[5];
    const float* bv    = (const float*)d_in[6];
    const float* gamma = (const float*)d_in[7];
    float* out = (float*)d_out;

    qkv_kernel<<<dim3((B_ * N_) / 32, 2), 128>>>(x, Wq, bq, Wk, bk, Wv, bv);
    attn_mma_kernel<<<dim3(N_ / MT, KS2, B_), 256>>>();
    combine_kernel<<<dim3((B_ * N_) / 128, 4), 128>>>(x, gamma, out);
}

// round 13
// speedup vs baseline: 1.1499x; 1.1499x over previous
#include <cuda_runtime.h>
#include <cstdint>

// Shapes (fixed)
constexpr int B_   = 2;
constexpr int C_   = 64;
constexpr int CQK_ = 8;
constexpr int N_   = 4096;

constexpr int KS2 = 8;       // key splits
constexpr int MT  = 128;     // queries per CTA (4 warps x 2 m16 tiles)
constexpr int NK  = 128;     // keys staged per tile
constexpr int VSTRIDE = 72;  // padded floats per key row in smem (conflict-free)

// ---------------- scratch ----------------
__device__ float g_q[B_ * N_ * CQK_];          // [B][N][8] (pre-scaled by log2e)
__device__ float g_k[B_ * N_ * CQK_];          // [B][N][8]
__device__ float g_v[B_ * N_ * C_];            // [B][N][64] key-major, tf32-rounded
__device__ float g_pacc[B_ * KS2 * N_ * C_];   // [B][S][q][64]
__device__ float g_pden[B_ * KS2 * N_];        // [B][S][q]

// ---------------- helpers ----------------
__device__ __forceinline__ unsigned long long fma2(unsigned long long a, unsigned long long b, unsigned long long c) {
    unsigned long long d;
    asm("fma.rn.f32x2 %0, %1, %2, %3;" : "=l"(d) : "l"(a), "l"(b), "l"(c));
    return d;
}
__device__ __forceinline__ unsigned long long mul2(unsigned long long a, unsigned long long b) {
    unsigned long long d;
    asm("mul.rn.f32x2 %0, %1, %2;" : "=l"(d) : "l"(a), "l"(b));
    return d;
}
__device__ __forceinline__ unsigned long long pack2(float lo, float hi) {
    unsigned long long r;
    asm("mov.b64 %0, {%1, %2};" : "=l"(r) : "f"(lo), "f"(hi));
    return r;
}
__device__ __forceinline__ float hadd2(unsigned long long a) {
    float lo, hi;
    asm("mov.b64 {%0, %1}, %2;" : "=f"(lo), "=f"(hi) : "l"(a));
    return lo + hi;
}
__device__ __forceinline__ float ex2f(float x) {
    float r;
    asm("ex2.approx.f32 %0, %1;" : "=f"(r) : "f"(x));
    return r;
}
__device__ __forceinline__ uint32_t f2tf32(float f) {
    uint32_t r;
    asm("cvt.rna.tf32.f32 %0, %1;" : "=r"(r) : "f"(f));
    return r;
}
// D[16x8] += A[16x8, tf32 row] * B[8x8, tf32 col]; accumulate in place
__device__ __forceinline__ void mma_tf32(float* d, const uint32_t* a, uint32_t b0, uint32_t b1) {
    asm volatile(
        "mma.sync.aligned.m16n8k8.row.col.f32.tf32.tf32.f32 "
        "{%0,%1,%2,%3}, {%4,%5,%6,%7}, {%8,%9}, {%0,%1,%2,%3};"
        : "+f"(d[0]), "+f"(d[1]), "+f"(d[2]), "+f"(d[3])
        : "r"(a[0]), "r"(a[1]), "r"(a[2]), "r"(a[3]), "r"(b0), "r"(b1));
}

// ============================================================================
// Kernel 1: QKV projection. Grid (256, 3) x 128 threads.
//  y=0: w0=q[0:8], w1=k[0:8], w2=v[0:8],  w3=v[8:16]
//  y=1: v[16:40]  (4 warps x 6 ch)
//  y=2: v[40:64]  (4 warps x 6 ch)
// Single-pass xr[64] (max loads in flight). q pre-scaled by log2(e);
// V stored key-major [B][N][64], tf32-rounded.
// ============================================================================
__global__ __launch_bounds__(128) void qkv_kernel(
    const float* __restrict__ x,
    const float* __restrict__ Wq, const float* __restrict__ bq,
    const float* __restrict__ Wk, const float* __restrict__ bk,
    const float* __restrict__ Wv, const float* __restrict__ bv)
{
    __shared__ float swq[CQK_ * C_], swk[CQK_ * C_], swv[24 * C_];
    __shared__ float sbq[CQK_], sbk[CQK_], sbv[24];
    const int tid = threadIdx.x, wid = tid >> 5, lid = tid & 31;
    const int y = blockIdx.y;

    if (y == 0) {
        for (int i = tid; i < CQK_ * C_; i += 128) { swq[i] = Wq[i]; swk[i] = Wk[i]; }
        for (int i = tid; i < 16 * C_; i += 128) { swv[i] = Wv[i]; }
        if (tid < CQK_) { sbq[tid] = bq[tid]; sbk[tid] = bk[tid]; }
        if (tid < 16)   { sbv[tid] = bv[tid]; }
    } else {
        const int base = 16 + (y - 1) * 24;
        for (int i = tid; i < 24 * C_; i += 128) { swv[i] = Wv[base * C_ + i]; }
        if (tid < 24) { sbv[tid] = bv[base + tid]; }
    }
    __syncthreads();

    const int pos = blockIdx.x * 32 + lid;     // b*N + n
    const int b = pos >> 12;
    const int n = pos & (N_ - 1);
    const float* xb = x + (size_t)b * C_ * N_ + n;

    float xr[C_];
#pragma unroll
    for (int c = 0; c < C_; c++) xr[c] = xb[(size_t)c * N_];

    if (y == 0 && wid < 2) {
        const float* W  = wid ? swk : swq;
        const float* bb = wid ? sbk : sbq;
        const float scale = wid ? 1.0f : 1.44269504088896f;   // log2(e) into q
        float o[CQK_];
#pragma unroll
        for (int j = 0; j < CQK_; j++) {
            float a = bb[j];
#pragma unroll
            for (int c = 0; c < C_; c++) a += W[j * C_ + c] * xr[c];
            o[j] = a * scale;
        }
        float* dst = (wid ? g_k : g_q) + (size_t)pos * CQK_;
        ((float4*)dst)[0] = make_float4(o[0], o[1], o[2], o[3]);
        ((float4*)dst)[1] = make_float4(o[4], o[5], o[6], o[7]);
        return;
    }

    float* vo = g_v + (size_t)pos * C_;
    if (y == 0) {
        // v channels [ (wid-2)*8, +8 ), weights at swv rows 0..15
        const int c0 = (wid - 2) * 8;
        float acc[8];
#pragma unroll
        for (int j = 0; j < 8; j++) acc[j] = sbv[c0 + j];
#pragma unroll
        for (int c = 0; c < C_; c++) {
            const float xv = xr[c];
#pragma unroll
            for (int j = 0; j < 8; j++) acc[j] += swv[(c0 + j) * C_ + c] * xv;
        }
        *(float4*)(vo + c0)     = make_float4(
            __uint_as_float(f2tf32(acc[0])), __uint_as_float(f2tf32(acc[1])),
            __uint_as_float(f2tf32(acc[2])), __uint_as_float(f2tf32(acc[3])));
        *(float4*)(vo + c0 + 4) = make_float4(
            __uint_as_float(f2tf32(acc[4])), __uint_as_float(f2tf32(acc[5])),
            __uint_as_float(f2tf32(acc[6])), __uint_as_float(f2tf32(acc[7])));
    } else {
        // v channels [16 + (y-1)*24 + wid*6, +6)
        const int rel0 = wid * 6;
        const int g0 = 16 + (y - 1) * 24 + rel0;
        float acc[6];
#pragma unroll
        for (int j = 0; j < 6; j++) acc[j] = sbv[rel0 + j];
#pragma unroll
        for (int c = 0; c < C_; c++) {
            const float xv = xr[c];
#pragma unroll
            for (int j = 0; j < 6; j++) acc[j] += swv[(rel0 + j) * C_ + c] * xv;
        }
#pragma unroll
        for (int j = 0; j < 6; j += 2) {
            *(float2*)(vo + g0 + j) = make_float2(
                __uint_as_float(f2tf32(acc[j])), __uint_as_float(f2tf32(acc[j + 1])));
        }
    }
}

// ============================================================================
// Kernel 2: flash attention, PV on mma.sync tf32 (m16n8k8), 2 q-tiles/warp.
// Grid (32, KS2=8, 2), 128 threads = 4 warps; warp w owns queries
// [32w, 32w+32) as two m16 tiles sharing K fragments and B-fragment loads.
// P fed to mma as raw f32 bits (tf32 truncation) — no cvt on critical path.
// ============================================================================
__global__ __launch_bounds__(128, 3) void attn_mma_kernel()
{
    __shared__ float4 skt[NK * 2];                // K tile [128 keys][8]  (4 KB)
    __shared__ float  svt[NK * VSTRIDE];          // V tile [128 keys][72] (36 KB)

    const int tid = threadIdx.x, wid = tid >> 5, lane = tid & 31;
    const int b = blockIdx.z, sp = blockIdx.y, qt = blockIdx.x;
    const int grp = lane >> 2;        // 0..7
    const int cq  = lane & 3;         // 0..3

    const int qA0 = qt * MT + wid * 32 + grp;     // tile A rows: qA0, qA0+8
    const int qB0 = qA0 + 16;                     // tile B rows: qB0, qB0+8

    // load 4 query rows, packed for fma2
    unsigned long long qqA0[4], qqA1[4], qqB0[4], qqB1[4];
    {
        const float4* p;
        p = (const float4*)(g_q + ((size_t)b * N_ + qA0) * CQK_);
        qqA0[0] = pack2(p[0].x, p[0].y); qqA0[1] = pack2(p[0].z, p[0].w);
        qqA0[2] = pack2(p[1].x, p[1].y); qqA0[3] = pack2(p[1].z, p[1].w);
        p = (const float4*)(g_q + ((size_t)b * N_ + qA0 + 8) * CQK_);
        qqA1[0] = pack2(p[0].x, p[0].y); qqA1[1] = pack2(p[0].z, p[0].w);
        qqA1[2] = pack2(p[1].x, p[1].y); qqA1[3] = pack2(p[1].z, p[1].w);
        p = (const float4*)(g_q + ((size_t)b * N_ + qB0) * CQK_);
        qqB0[0] = pack2(p[0].x, p[0].y); qqB0[1] = pack2(p[0].z, p[0].w);
        qqB0[2] = pack2(p[1].x, p[1].y); qqB0[3] = pack2(p[1].z, p[1].w);
        p = (const float4*)(g_q + ((size_t)b * N_ + qB0 + 8) * CQK_);
        qqB1[0] = pack2(p[0].x, p[0].y); qqB1[1] = pack2(p[0].z, p[0].w);
        qqB1[2] = pack2(p[1].x, p[1].y); qqB1[3] = pack2(p[1].z, p[1].w);
    }

    float dA[8][4], dB[8][4];
#pragma unroll
    for (int j = 0; j < 8; j++) {
        dA[j][0] = dA[j][1] = dA[j][2] = dA[j][3] = 0.0f;
        dB[j][0] = dB[j][1] = dB[j][2] = dB[j][3] = 0.0f;
    }
    float denA0 = 0.f, denA1 = 0.f, denB0 = 0.f, denB1 = 0.f;

    const int kbase0 = sp * (N_ / KS2);
    for (int t = 0; t < (N_ / KS2) / NK; t++) {
        const int kstart = kbase0 + t * NK;
        __syncthreads();
        // stage K: 256 float4 over 128 threads
        const float4* kg = (const float4*)(g_k + ((size_t)b * N_ + kstart) * CQK_);
        skt[tid] = kg[tid];
        skt[tid + 128] = kg[tid + 128];
        // stage V: 2048 float4 -> [key][72]
        const float4* vg = (const float4*)(g_v + ((size_t)b * N_ + kstart) * C_);
#pragma unroll
        for (int i = tid; i < NK * 16; i += 128) {
            const int key = i >> 4, c4 = i & 15;
            *(float4*)(svt + key * VSTRIDE + c4 * 4) = vg[i];
        }
        __syncthreads();

#pragma unroll 2
        for (int s = 0; s < NK / 8; s++) {
            const int k0 = s * 8;
            const float4 kA0 = skt[(k0 + cq) * 2],     kA1 = skt[(k0 + cq) * 2 + 1];
            const float4 kB0 = skt[(k0 + cq + 4) * 2], kB1 = skt[(k0 + cq + 4) * 2 + 1];
            const unsigned long long kAp[4] = { pack2(kA0.x, kA0.y), pack2(kA0.z, kA0.w),
                                                pack2(kA1.x, kA1.y), pack2(kA1.z, kA1.w) };
            const unsigned long long kBp[4] = { pack2(kB0.x, kB0.y), pack2(kB0.z, kB0.w),
                                                pack2(kB1.x, kB1.y), pack2(kB1.z, kB1.w) };

            unsigned long long e;
            // tile A
            e = mul2(qqA0[3], kAp[3]); e = fma2(qqA0[2], kAp[2], e);
            e = fma2(qqA0[1], kAp[1], e); e = fma2(qqA0[0], kAp[0], e);
            const float pa00 = ex2f(hadd2(e));
            e = mul2(qqA1[3], kAp[3]); e = fma2(qqA1[2], kAp[2], e);
            e = fma2(qqA1[1], kAp[1], e); e = fma2(qqA1[0], kAp[0], e);
            const float pa10 = ex2f(hadd2(e));
            e = mul2(qqA0[3], kBp[3]); e = fma2(qqA0[2], kBp[2], e);
            e = fma2(qqA0[1], kBp[1], e); e = fma2(qqA0[0], kBp[0], e);
            const float pa01 = ex2f(hadd2(e));
            e = mul2(qqA1[3], kBp[3]); e = fma2(qqA1[2], kBp[2], e);
            e = fma2(qqA1[1], kBp[1], e); e = fma2(qqA1[0], kBp[0], e);
            const float pa11 = ex2f(hadd2(e));
            // tile B
            e = mul2(qqB0[3], kAp[3]); e = fma2(qqB0[2], kAp[2], e);
            e = fma2(qqB0[1], kAp[1], e); e = fma2(qqB0[0], kAp[0], e);
            const float pb00 = ex2f(hadd2(e));
            e = mul2(qqB1[3], kAp[3]); e = fma2(qqB1[2], kAp[2], e);
            e = fma2(qqB1[1], kAp[1], e); e = fma2(qqB1[0], kAp[0], e);
            const float pb10 = ex2f(hadd2(e));
            e = mul2(qqB0[3], kBp[3]); e = fma2(qqB0[2], kBp[2], e);
            e = fma2(qqB0[1], kBp[1], e); e = fma2(qqB0[0], kBp[0], e);
            const float pb01 = ex2f(hadd2(e));
            e = mul2(qqB1[3], kBp[3]); e = fma2(qqB1[2], kBp[2], e);
            e = fma2(qqB1[1], kBp[1], e); e = fma2(qqB1[0], kBp[0], e);
            const float pb11 = ex2f(hadd2(e));

            denA0 += pa00 + pa01;  denA1 += pa10 + pa11;
            denB0 += pb00 + pb01;  denB1 += pb10 + pb11;

            // raw f32 bits as tf32 (truncation; no cvt on the chain)
            const uint32_t aA[4] = { __float_as_uint(pa00), __float_as_uint(pa10),
                                     __float_as_uint(pa01), __float_as_uint(pa11) };
            const uint32_t aB[4] = { __float_as_uint(pb00), __float_as_uint(pb10),
                                     __float_as_uint(pb01), __float_as_uint(pb11) };

            const float* vr0 = svt + (k0 + cq) * VSTRIDE + grp;
            const float* vr1 = vr0 + 4 * VSTRIDE;
#pragma unroll
            for (int j = 0; j < 8; j++) {
                const uint32_t b0 = __float_as_uint(vr0[8 * j]);
                const uint32_t b1 = __float_as_uint(vr1[8 * j]);
                mma_tf32(dA[j], aA, b0, b1);
                mma_tf32(dB[j], aB, b0, b1);
            }
        }
    }

    denA0 += __shfl_xor_sync(0xFFFFFFFFu, denA0, 1);
    denA0 += __shfl_xor_sync(0xFFFFFFFFu, denA0, 2);
    denA1 += __shfl_xor_sync(0xFFFFFFFFu, denA1, 1);
    denA1 += __shfl_xor_sync(0xFFFFFFFFu, denA1, 2);
    denB0 += __shfl_xor_sync(0xFFFFFFFFu, denB0, 1);
    denB0 += __shfl_xor_sync(0xFFFFFFFFu, denB0, 2);
    denB1 += __shfl_xor_sync(0xFFFFFFFFu, denB1, 1);
    denB1 += __shfl_xor_sync(0xFFFFFFFFu, denB1, 2);

    const size_t pbase = ((size_t)(b * KS2 + sp) * N_);
    float* pA0 = g_pacc + (pbase + qA0) * C_;
    float* pA1 = g_pacc + (pbase + qA0 + 8) * C_;
    float* pB0 = g_pacc + (pbase + qB0) * C_;
    float* pB1 = g_pacc + (pbase + qB0 + 8) * C_;
#pragma unroll
    for (int j = 0; j < 8; j++) {
        *(float2*)(pA0 + 8 * j + 2 * cq) = make_float2(dA[j][0], dA[j][1]);
        *(float2*)(pA1 + 8 * j + 2 * cq) = make_float2(dA[j][2], dA[j][3]);
        *(float2*)(pB0 + 8 * j + 2 * cq) = make_float2(dB[j][0], dB[j][1]);
        *(float2*)(pB1 + 8 * j + 2 * cq) = make_float2(dB[j][2], dB[j][3]);
    }
    if (cq == 0) {
        float* pd = g_pden + pbase;
        pd[qA0] = denA0;  pd[qA0 + 8] = denA1;
        pd[qB0] = denB0;  pd[qB0 + 8] = denB1;
    }
}

// ============================================================================
// Kernel 3: combine KS2 split partials + residual.
// Grid (64, 4) x 128: thread = (b, n), blockIdx.y = channel quarter.
// ============================================================================
__global__ __launch_bounds__(128) void combine_kernel(
    const float* __restrict__ x,
    const float* __restrict__ gamma,
    float* __restrict__ out)
{
    const int t = blockIdx.x * 128 + threadIdx.x;   // 0..B*N-1
    const int b = t >> 12;
    const int n = t & (N_ - 1);
    const int c4base = blockIdx.y * 4;              // 4 c4-chunks per block row

    float den = 0.0f;
#pragma unroll
    for (int s = 0; s < KS2; s++) den += g_pden[(size_t)(b * KS2 + s) * N_ + n];
    const float scale = gamma[0] / den;

#pragma unroll
    for (int c4 = c4base; c4 < c4base + 4; c4++) {
        float sx = 0.f, sy = 0.f, sz = 0.f, sw = 0.f;
#pragma unroll
        for (int s = 0; s < KS2; s++) {
            const float4 u = ((const float4*)(g_pacc + (((size_t)(b * KS2 + s) * N_) + n) * C_))[c4];
            sx += u.x; sy += u.y; sz += u.z; sw += u.w;
        }
        size_t o = ((size_t)b * C_ + c4 * 4) * N_ + n;
        out[o] = fmaf(scale, sx, x[o]); o += N_;
        out[o] = fmaf(scale, sy, x[o]); o += N_;
        out[o] = fmaf(scale, sz, x[o]); o += N_;
        out[o] = fmaf(scale, sw, x[o]);
    }
}

// ============================================================================
extern "C" void kernel_launch(void* const* d_in, const int* in_sizes, int n_in,
                              void* d_out, int out_size)
{
    const float* x     = (const float*)d_in[0];
    const float* Wq    = (const float*)d_in[1];
    const float* bq    = (const float*)d_in[2];
    const float* Wk    = (const float*)d_in[3];
    const float* bk    = (const float*)d_in[4];
    const float* Wv    = (const float*)d_in[5];
    const float* bv    = (const float*)d_in[6];
    const float* gamma = (const float*)d_in[7];
    float* out = (float*)d_out;

    qkv_kernel<<<dim3((B_ * N_) / 32, 3), 128>>>(x, Wq, bq, Wk, bk, Wv, bv);
    attn_mma_kernel<<<dim3(N_ / MT, KS2, B_), 128>>>();
    combine_kernel<<<dim3((B_ * N_) / 128, 4), 128>>>(x, gamma, out);
}

// round 17
// speedup vs baseline: 1.1942x; 1.0386x over previous
#include <cuda_runtime.h>
#include <cstdint>

// Shapes (fixed)
constexpr int B_   = 2;
constexpr int C_   = 64;
constexpr int CQK_ = 8;
constexpr int N_   = 4096;

constexpr int KS2 = 8;       // key splits
constexpr int MT  = 128;     // queries per CTA (4 warps x 2 m16 tiles)
constexpr int NK  = 128;     // keys staged per tile
constexpr int VSTRIDE = 72;  // padded floats per key row in smem (conflict-free)

// ---------------- scratch ----------------
__device__ float g_q[B_ * N_ * CQK_];          // [B][N][8] (pre-scaled by log2e)
__device__ float g_k[B_ * N_ * CQK_];          // [B][N][8]
__device__ float g_v[B_ * N_ * C_];            // [B][N][64] key-major, tf32-rounded
__device__ float g_pacc[B_ * KS2 * N_ * C_];   // [B][S][q][64]
__device__ float g_pden[B_ * KS2 * N_];        // [B][S][q]

// ---------------- helpers ----------------
__device__ __forceinline__ unsigned long long fma2(unsigned long long a, unsigned long long b, unsigned long long c) {
    unsigned long long d;
    asm("fma.rn.f32x2 %0, %1, %2, %3;" : "=l"(d) : "l"(a), "l"(b), "l"(c));
    return d;
}
__device__ __forceinline__ unsigned long long mul2(unsigned long long a, unsigned long long b) {
    unsigned long long d;
    asm("mul.rn.f32x2 %0, %1, %2;" : "=l"(d) : "l"(a), "l"(b));
    return d;
}
__device__ __forceinline__ unsigned long long pack2(float lo, float hi) {
    unsigned long long r;
    asm("mov.b64 %0, {%1, %2};" : "=l"(r) : "f"(lo), "f"(hi));
    return r;
}
__device__ __forceinline__ float hadd2(unsigned long long a) {
    float lo, hi;
    asm("mov.b64 {%0, %1}, %2;" : "=f"(lo), "=f"(hi) : "l"(a));
    return lo + hi;
}
__device__ __forceinline__ float ex2f(float x) {
    float r;
    asm("ex2.approx.f32 %0, %1;" : "=f"(r) : "f"(x));
    return r;
}
__device__ __forceinline__ uint32_t f2tf32(float f) {
    uint32_t r;
    asm("cvt.rna.tf32.f32 %0, %1;" : "=r"(r) : "f"(f));
    return r;
}
// D[16x8] += A[16x8, tf32 row] * B[8x8, tf32 col]; accumulate in place
__device__ __forceinline__ void mma_tf32(float* d, const uint32_t* a, uint32_t b0, uint32_t b1) {
    asm volatile(
        "mma.sync.aligned.m16n8k8.row.col.f32.tf32.tf32.f32 "
        "{%0,%1,%2,%3}, {%4,%5,%6,%7}, {%8,%9}, {%0,%1,%2,%3};"
        : "+f"(d[0]), "+f"(d[1]), "+f"(d[2]), "+f"(d[3])
        : "r"(a[0]), "r"(a[1]), "r"(a[2]), "r"(a[3]), "r"(b0), "r"(b1));
}

// ============================================================================
// Kernel 1: QKV projection (round-10 proven, 13.8us). Grid (256, 2) x 128.
//  y=0: w0=q[0:8], w1=k[0:8], w2=v[0:8],  w3=v[8:16]
//  y=1: w0=v[16:28], w1=v[28:40], w2=v[40:52], w3=v[52:64]
// q pre-scaled by log2(e); V stored key-major [B][N][64], tf32-rounded.
// ============================================================================
__global__ __launch_bounds__(128) void qkv_kernel(
    const float* __restrict__ x,
    const float* __restrict__ Wq, const float* __restrict__ bq,
    const float* __restrict__ Wk, const float* __restrict__ bk,
    const float* __restrict__ Wv, const float* __restrict__ bv)
{
    __shared__ float swq[CQK_ * C_], swk[CQK_ * C_], swv[C_ * C_];
    __shared__ float sbq[CQK_], sbk[CQK_], sbv[C_];
    const int tid = threadIdx.x, wid = tid >> 5, lid = tid & 31;
    const int y = blockIdx.y;

    if (y == 0) {
        for (int i = tid; i < CQK_ * C_; i += 128) { swq[i] = Wq[i]; swk[i] = Wk[i]; }
        for (int i = tid; i < 16 * C_; i += 128) { swv[i] = Wv[i]; }
        if (tid < CQK_) { sbq[tid] = bq[tid]; sbk[tid] = bk[tid]; }
        if (tid < 16)   { sbv[tid] = bv[tid]; }
    } else {
        for (int i = tid; i < 48 * C_; i += 128) { swv[16 * C_ + i] = Wv[16 * C_ + i]; }
        if (tid < 48) { sbv[16 + tid] = bv[16 + tid]; }
    }
    __syncthreads();

    const int pos = blockIdx.x * 32 + lid;     // b*N + n
    const int b = pos >> 12;
    const int n = pos & (N_ - 1);

    float xr[C_];
    const float* xb = x + (size_t)b * C_ * N_ + n;
#pragma unroll
    for (int c = 0; c < C_; c++) xr[c] = xb[(size_t)c * N_];

    if (y == 0 && wid < 2) {
        const float* W  = wid ? swk : swq;
        const float* bb = wid ? sbk : sbq;
        const float scale = wid ? 1.0f : 1.44269504088896f;   // log2(e) into q
        float o[CQK_];
#pragma unroll
        for (int j = 0; j < CQK_; j++) {
            float a = bb[j];
#pragma unroll
            for (int c = 0; c < C_; c++) a += W[j * C_ + c] * xr[c];
            o[j] = a * scale;
        }
        float* dst = (wid ? g_k : g_q) + (size_t)pos * CQK_;
        ((float4*)dst)[0] = make_float4(o[0], o[1], o[2], o[3]);
        ((float4*)dst)[1] = make_float4(o[4], o[5], o[6], o[7]);
        return;
    }

    int c0, cnt;
    if (y == 0) { c0 = (wid - 2) * 8; cnt = 8; }       // v[0:8], v[8:16]
    else        { c0 = 16 + wid * 12; cnt = 12; }      // v[16:64] in 12s
    float* vo = g_v + (size_t)pos * C_;
    for (int jj = 0; jj < cnt; jj += 4) {
        float a0 = sbv[c0 + jj], a1 = sbv[c0 + jj + 1], a2 = sbv[c0 + jj + 2], a3 = sbv[c0 + jj + 3];
#pragma unroll
        for (int c = 0; c < C_; c++) {
            const float xv = xr[c];
            a0 += swv[(c0 + jj)     * C_ + c] * xv;
            a1 += swv[(c0 + jj + 1) * C_ + c] * xv;
            a2 += swv[(c0 + jj + 2) * C_ + c] * xv;
            a3 += swv[(c0 + jj + 3) * C_ + c] * xv;
        }
        *(float4*)(vo + c0 + jj) = make_float4(
            __uint_as_float(f2tf32(a0)), __uint_as_float(f2tf32(a1)),
            __uint_as_float(f2tf32(a2)), __uint_as_float(f2tf32(a3)));
    }
}

// ============================================================================
// Kernel 2: flash attention, PV on mma.sync tf32 (m16n8k8), 2 q-tiles/warp
// (round-13 proven, rel_err 8e-5). Grid (32, KS2=8, 2), 128 threads = 4 warps;
// warp w owns queries [32w, 32w+32) as two m16 tiles sharing K fragments and
// B-fragment loads. P fed to mma as raw f32 bits (tf32 truncation).
// ============================================================================
__global__ __launch_bounds__(128, 3) void attn_mma_kernel()
{
    __shared__ float4 skt[NK * 2];                // K tile [128 keys][8]  (4 KB)
    __shared__ float  svt[NK * VSTRIDE];          // V tile [128 keys][72] (36 KB)

    const int tid = threadIdx.x, wid = tid >> 5, lane = tid & 31;
    const int b = blockIdx.z, sp = blockIdx.y, qt = blockIdx.x;
    const int grp = lane >> 2;        // 0..7
    const int cq  = lane & 3;         // 0..3

    const int qA0 = qt * MT + wid * 32 + grp;     // tile A rows: qA0, qA0+8
    const int qB0 = qA0 + 16;                     // tile B rows: qB0, qB0+8

    // load 4 query rows, packed for fma2
    unsigned long long qqA0[4], qqA1[4], qqB0[4], qqB1[4];
    {
        const float4* p;
        p = (const float4*)(g_q + ((size_t)b * N_ + qA0) * CQK_);
        qqA0[0] = pack2(p[0].x, p[0].y); qqA0[1] = pack2(p[0].z, p[0].w);
        qqA0[2] = pack2(p[1].x, p[1].y); qqA0[3] = pack2(p[1].z, p[1].w);
        p = (const float4*)(g_q + ((size_t)b * N_ + qA0 + 8) * CQK_);
        qqA1[0] = pack2(p[0].x, p[0].y); qqA1[1] = pack2(p[0].z, p[0].w);
        qqA1[2] = pack2(p[1].x, p[1].y); qqA1[3] = pack2(p[1].z, p[1].w);
        p = (const float4*)(g_q + ((size_t)b * N_ + qB0) * CQK_);
        qqB0[0] = pack2(p[0].x, p[0].y); qqB0[1] = pack2(p[0].z, p[0].w);
        qqB0[2] = pack2(p[1].x, p[1].y); qqB0[3] = pack2(p[1].z, p[1].w);
        p = (const float4*)(g_q + ((size_t)b * N_ + qB0 + 8) * CQK_);
        qqB1[0] = pack2(p[0].x, p[0].y); qqB1[1] = pack2(p[0].z, p[0].w);
        qqB1[2] = pack2(p[1].x, p[1].y); qqB1[3] = pack2(p[1].z, p[1].w);
    }

    float dA[8][4], dB[8][4];
#pragma unroll
    for (int j = 0; j < 8; j++) {
        dA[j][0] = dA[j][1] = dA[j][2] = dA[j][3] = 0.0f;
        dB[j][0] = dB[j][1] = dB[j][2] = dB[j][3] = 0.0f;
    }
    float denA0 = 0.f, denA1 = 0.f, denB0 = 0.f, denB1 = 0.f;

    const int kbase0 = sp * (N_ / KS2);
    for (int t = 0; t < (N_ / KS2) / NK; t++) {
        const int kstart = kbase0 + t * NK;
        __syncthreads();
        // stage K: 256 float4 over 128 threads
        const float4* kg = (const float4*)(g_k + ((size_t)b * N_ + kstart) * CQK_);
        skt[tid] = kg[tid];
        skt[tid + 128] = kg[tid + 128];
        // stage V: 2048 float4 -> [key][72]
        const float4* vg = (const float4*)(g_v + ((size_t)b * N_ + kstart) * C_);
#pragma unroll
        for (int i = tid; i < NK * 16; i += 128) {
            const int key = i >> 4, c4 = i & 15;
            *(float4*)(svt + key * VSTRIDE + c4 * 4) = vg[i];
        }
        __syncthreads();

#pragma unroll 2
        for (int s = 0; s < NK / 8; s++) {
            const int k0 = s * 8;
            const float4 kA0 = skt[(k0 + cq) * 2],     kA1 = skt[(k0 + cq) * 2 + 1];
            const float4 kB0 = skt[(k0 + cq + 4) * 2], kB1 = skt[(k0 + cq + 4) * 2 + 1];
            const unsigned long long kAp[4] = { pack2(kA0.x, kA0.y), pack2(kA0.z, kA0.w),
                                                pack2(kA1.x, kA1.y), pack2(kA1.z, kA1.w) };
            const unsigned long long kBp[4] = { pack2(kB0.x, kB0.y), pack2(kB0.z, kB0.w),
                                                pack2(kB1.x, kB1.y), pack2(kB1.z, kB1.w) };

            unsigned long long e;
            // tile A
            e = mul2(qqA0[3], kAp[3]); e = fma2(qqA0[2], kAp[2], e);
            e = fma2(qqA0[1], kAp[1], e); e = fma2(qqA0[0], kAp[0], e);
            const float pa00 = ex2f(hadd2(e));
            e = mul2(qqA1[3], kAp[3]); e = fma2(qqA1[2], kAp[2], e);
            e = fma2(qqA1[1], kAp[1], e); e = fma2(qqA1[0], kAp[0], e);
            const float pa10 = ex2f(hadd2(e));
            e = mul2(qqA0[3], kBp[3]); e = fma2(qqA0[2], kBp[2], e);
            e = fma2(qqA0[1], kBp[1], e); e = fma2(qqA0[0], kBp[0], e);
            const float pa01 = ex2f(hadd2(e));
            e = mul2(qqA1[3], kBp[3]); e = fma2(qqA1[2], kBp[2], e);
            e = fma2(qqA1[1], kBp[1], e); e = fma2(qqA1[0], kBp[0], e);
            const float pa11 = ex2f(hadd2(e));
            // tile B
            e = mul2(qqB0[3], kAp[3]); e = fma2(qqB0[2], kAp[2], e);
            e = fma2(qqB0[1], kAp[1], e); e = fma2(qqB0[0], kAp[0], e);
            const float pb00 = ex2f(hadd2(e));
            e = mul2(qqB1[3], kAp[3]); e = fma2(qqB1[2], kAp[2], e);
            e = fma2(qqB1[1], kAp[1], e); e = fma2(qqB1[0], kAp[0], e);
            const float pb10 = ex2f(hadd2(e));
            e = mul2(qqB0[3], kBp[3]); e = fma2(qqB0[2], kBp[2], e);
            e = fma2(qqB0[1], kBp[1], e); e = fma2(qqB0[0], kBp[0], e);
            const float pb01 = ex2f(hadd2(e));
            e = mul2(qqB1[3], kBp[3]); e = fma2(qqB1[2], kBp[2], e);
            e = fma2(qqB1[1], kBp[1], e); e = fma2(qqB1[0], kBp[0], e);
            const float pb11 = ex2f(hadd2(e));

            denA0 += pa00 + pa01;  denA1 += pa10 + pa11;
            denB0 += pb00 + pb01;  denB1 += pb10 + pb11;

            // raw f32 bits as tf32 (truncation; no cvt on the chain)
            const uint32_t aA[4] = { __float_as_uint(pa00), __float_as_uint(pa10),
                                     __float_as_uint(pa01), __float_as_uint(pa11) };
            const uint32_t aB[4] = { __float_as_uint(pb00), __float_as_uint(pb10),
                                     __float_as_uint(pb01), __float_as_uint(pb11) };

            const float* vr0 = svt + (k0 + cq) * VSTRIDE + grp;
            const float* vr1 = vr0 + 4 * VSTRIDE;
#pragma unroll
            for (int j = 0; j < 8; j++) {
                const uint32_t b0 = __float_as_uint(vr0[8 * j]);
                const uint32_t b1 = __float_as_uint(vr1[8 * j]);
                mma_tf32(dA[j], aA, b0, b1);
                mma_tf32(dB[j], aB, b0, b1);
            }
        }
    }

    denA0 += __shfl_xor_sync(0xFFFFFFFFu, denA0, 1);
    denA0 += __shfl_xor_sync(0xFFFFFFFFu, denA0, 2);
    denA1 += __shfl_xor_sync(0xFFFFFFFFu, denA1, 1);
    denA1 += __shfl_xor_sync(0xFFFFFFFFu, denA1, 2);
    denB0 += __shfl_xor_sync(0xFFFFFFFFu, denB0, 1);
    denB0 += __shfl_xor_sync(0xFFFFFFFFu, denB0, 2);
    denB1 += __shfl_xor_sync(0xFFFFFFFFu, denB1, 1);
    denB1 += __shfl_xor_sync(0xFFFFFFFFu, denB1, 2);

    const size_t pbase = ((size_t)(b * KS2 + sp) * N_);
    float* pA0 = g_pacc + (pbase + qA0) * C_;
    float* pA1 = g_pacc + (pbase + qA0 + 8) * C_;
    float* pB0 = g_pacc + (pbase + qB0) * C_;
    float* pB1 = g_pacc + (pbase + qB0 + 8) * C_;
#pragma unroll
    for (int j = 0; j < 8; j++) {
        *(float2*)(pA0 + 8 * j + 2 * cq) = make_float2(dA[j][0], dA[j][1]);
        *(float2*)(pA1 + 8 * j + 2 * cq) = make_float2(dA[j][2], dA[j][3]);
        *(float2*)(pB0 + 8 * j + 2 * cq) = make_float2(dB[j][0], dB[j][1]);
        *(float2*)(pB1 + 8 * j + 2 * cq) = make_float2(dB[j][2], dB[j][3]);
    }
    if (cq == 0) {
        float* pd = g_pden + pbase;
        pd[qA0] = denA0;  pd[qA0 + 8] = denA1;
        pd[qB0] = denB0;  pd[qB0 + 8] = denB1;
    }
}

// ============================================================================
// Kernel 3: combine KS2 split partials + residual.
// Grid (64, 4) x 128: thread = (b, n), blockIdx.y = channel quarter.
// ============================================================================
__global__ __launch_bounds__(128) void combine_kernel(
    const float* __restrict__ x,
    const float* __restrict__ gamma,
    float* __restrict__ out)
{
    const int t = blockIdx.x * 128 + threadIdx.x;   // 0..B*N-1
    const int b = t >> 12;
    const int n = t & (N_ - 1);
    const int c4base = blockIdx.y * 4;              // 4 c4-chunks per block row

    float den = 0.0f;
#pragma unroll
    for (int s = 0; s < KS2; s++) den += g_pden[(size_t)(b * KS2 + s) * N_ + n];
    const float scale = gamma[0] / den;

#pragma unroll
    for (int c4 = c4base; c4 < c4base + 4; c4++) {
        float sx = 0.f, sy = 0.f, sz = 0.f, sw = 0.f;
#pragma unroll
        for (int s = 0; s < KS2; s++) {
            const float4 u = ((const float4*)(g_pacc + (((size_t)(b * KS2 + s) * N_) + n) * C_))[c4];
            sx += u.x; sy += u.y; sz += u.z; sw += u.w;
        }
        size_t o = ((size_t)b * C_ + c4 * 4) * N_ + n;
        out[o] = fmaf(scale, sx, x[o]); o += N_;
        out[o] = fmaf(scale, sy, x[o]); o += N_;
        out[o] = fmaf(scale, sz, x[o]); o += N_;
        out[o] = fmaf(scale, sw, x[o]);
    }
}

// ============================================================================
extern "C" void kernel_launch(void* const* d_in, const int* in_sizes, int n_in,
                              void* d_out, int out_size)
{
    const float* x     = (const float*)d_in[0];
    const float* Wq    = (const float*)d_in[1];
    const float* bq    = (const float*)d_in[2];
    const float* Wk    = (const float*)d_in[3];
    const float* bk    = (const float*)d_in[4];
    const float* Wv    = (const float*)d_in[5];
    const float* bv    = (const float*)d_in[6];
    const float* gamma = (const float*)d_in[7];
    float* out = (float*)d_out;

    qkv_kernel<<<dim3((B_ * N_) / 32, 2), 128>>>(x, Wq, bq, Wk, bk, Wv, bv);
    attn_mma_kernel<<<dim3(N_ / MT, KS2, B_), 128>>>();
    combine_kernel<<<dim3((B_ * N_) / 128, 4), 128>>>(x, gamma, out);
}